// round 14
// baseline (speedup 1.0000x reference)
#include <cuda_runtime.h>
#include <cuda_bf16.h>
#include <cstdint>

#define B_SZ 2048
#define H_SZ 512
#define D_SZ 32

// ---------------- scratch (device globals; no allocation allowed) ----------
__device__ __align__(16) __nv_bfloat16 g_H1h[B_SZ * H_SZ];
__device__ __align__(16) __nv_bfloat16 g_H1l[B_SZ * H_SZ];
__device__ __align__(16) float         g_D1 [B_SZ * H_SZ];   // 1 - h1^2
__device__ __align__(16) __nv_bfloat16 g_H2h[B_SZ * H_SZ];   // tanh2 split
__device__ __align__(16) __nv_bfloat16 g_H2l[B_SZ * H_SZ];
__device__ __align__(16) __nv_bfloat16 g_D2h[B_SZ * H_SZ];   // 1 - h2^2 split
__device__ __align__(16) __nv_bfloat16 g_D2l[B_SZ * H_SZ];
__device__ __align__(16) __nv_bfloat16 g_Bt0h[H_SZ * H_SZ];  // W2^T split
__device__ __align__(16) __nv_bfloat16 g_Bt0l[H_SZ * H_SZ];
__device__ __align__(16) __nv_bfloat16 g_Bdvh[H_SZ * H_SZ];  // E[n][k] split
__device__ __align__(16) __nv_bfloat16 g_Bdvl[H_SZ * H_SZ];
__device__ __align__(16) __nv_bfloat16 g_W3th[D_SZ * H_SZ];  // W3^T split [d][k]
__device__ __align__(16) __nv_bfloat16 g_W3tl[D_SZ * H_SZ];
__device__ float g_divpart[8 * B_SZ];

// ---------------- helpers ---------------------------------------------------
__device__ __forceinline__ void bf16split(float x, __nv_bfloat16& h, __nv_bfloat16& l) {
    h = __float2bfloat16_rn(x);
    l = __float2bfloat16_rn(x - __bfloat162float(h));
}
__device__ __forceinline__ uint32_t smem_u32(const void* p) {
    return (uint32_t)__cvta_generic_to_shared(p);
}
__device__ __forceinline__ void cp16(uint32_t dst, const void* src) {
    asm volatile("cp.async.cg.shared.global [%0], [%1], 16;" :: "r"(dst), "l"(src));
}
#define CP_COMMIT() asm volatile("cp.async.commit_group;" ::: "memory")
#define CP_WAIT(n)  asm volatile("cp.async.wait_group %0;" :: "n"(n) : "memory")

#define LDSM4(d, addr)                                                          \
    asm volatile("ldmatrix.sync.aligned.m8n8.x4.shared.b16 {%0,%1,%2,%3}, [%4];"\
        : "=r"((d)[0]), "=r"((d)[1]), "=r"((d)[2]), "=r"((d)[3]) : "r"(addr))

#define MMA_BF16(c, a, b0v, b1v)                                                \
    asm volatile("mma.sync.aligned.m16n8k16.row.col.f32.bf16.bf16.f32 "         \
        "{%0,%1,%2,%3},{%4,%5,%6,%7},{%8,%9},{%0,%1,%2,%3};"                    \
        : "+f"((c)[0]), "+f"((c)[1]), "+f"((c)[2]), "+f"((c)[3])                 \
        : "r"((a)[0]), "r"((a)[1]), "r"((a)[2]), "r"((a)[3]), "r"(b0v), "r"(b1v))

// ---------------------------------------------------------------------------
// K01 (merged): blocks [0,128): H1/D1;  blocks [128,384): Bt0/Bdv (+W3t)
// ---------------------------------------------------------------------------
__global__ void __launch_bounds__(512) k01_pre(const float* __restrict__ t,
                                               const float* __restrict__ x,
                                               const float* __restrict__ W1,
                                               const float* __restrict__ b1,
                                               const float* __restrict__ W2,
                                               const float* __restrict__ W3) {
    __shared__ __align__(16) char sbuf[2 * 32 * 33 * 4];
    const int bx  = blockIdx.x;
    const int tid = threadIdx.x;

    if (bx < 128) {
        // ------- k1 role: H1 = tanh([x,t]@W1+b1), split + D1 -------
        float (*sx)[33] = (float(*)[33])sbuf;
        const int b0 = bx * 16;
        const int m  = tid;
        for (int idx = m; idx < 16 * 33; idx += 512) {
            int r = idx / 33, j = idx % 33;
            sx[r][j] = (j == 32) ? t[0] : x[(b0 + r) * 33 + j];
        }
        float w[33];
#pragma unroll
        for (int j = 0; j < 33; j++) w[j] = W1[j * H_SZ + m];
        float bb = b1[m];
        __syncthreads();
#pragma unroll 4
        for (int r = 0; r < 16; r++) {
            float acc = bb;
#pragma unroll
            for (int j = 0; j < 33; j++) acc = fmaf(sx[r][j], w[j], acc);
            float h = tanhf(acc);
            const int o = (b0 + r) * H_SZ + m;
            bf16split(h, g_H1h[o], g_H1l[o]);
            g_D1[o] = 1.f - h * h;
        }
    } else {
        // ------- k0 role: Bt0 = split(W2^T); Bdv = split(E); W3t -------
        float (*tW2)[33] = (float(*)[33])sbuf;
        float (*sW3)[33] = (float(*)[33])(sbuf + 32 * 33 * 4);
        const int q  = bx - 128;
        const int kt = q & 15, nt = q >> 4;
        const int k0 = kt * 32, n0 = nt * 32;
        const int tx = tid & 31, tyh = tid >> 5;   // tx: 0..31, tyh: 0..15
#pragma unroll
        for (int yy = 0; yy < 2; yy++) {
            int ty = tyh + yy * 16;
            tW2[ty][tx] = W2[(k0 + ty) * H_SZ + n0 + tx];
            sW3[ty][tx] = W3[(k0 + ty) * D_SZ + tx];
        }
        __syncthreads();
#pragma unroll
        for (int yy = 0; yy < 2; yy++) {
            const int ty = tyh + yy * 16;
            const int n = n0 + ty;
            const int k = k0 + tx;
            bf16split(tW2[tx][ty], g_Bt0h[n * H_SZ + k], g_Bt0l[n * H_SZ + k]);
            float s = 0.f;
#pragma unroll
            for (int j = 0; j < D_SZ; j++)
                s = fmaf(W1[j * H_SZ + n], sW3[tx][j], s);
            bf16split(W2[n * H_SZ + k] * s, g_Bdvh[n * H_SZ + k], g_Bdvl[n * H_SZ + k]);
        }
        if (nt == 0) {   // W3t[d][k] = split(W3[k][d]) for this k-range
#pragma unroll
            for (int yy = 0; yy < 2; yy++) {
                const int d = tyh + yy * 16;
                bf16split(sW3[tx][d], g_W3th[d * H_SZ + k0 + tx],
                                      g_W3tl[d * H_SZ + k0 + tx]);
            }
        }
    }
}

// ---------------------------------------------------------------------------
// bf16-split mma.sync GEMM, cp.async 4-stage pipeline (r7 config, proven).
// CTA tile 128(M) x 64(N), K=512 in 16 chunks of 32. grid (16,8), 256 thr.
// 8 warps: 4m x 2n, warp tile 32x32.
// MODE 0: C = H1 @ W2   -> H2 = tanh(C + b2) split, D2 = 1-H2^2 split
// MODE 1: C = D2 @ E^T  -> divpart[ny][row] = sum_col D1[row,col]*C[row,col]
// ---------------------------------------------------------------------------
#define SA_H 0
#define SA_L 10240
#define SB_H 20480
#define SB_L 25600
#define STG  30720
#define NSTAGE 4
#define GEMM_SMEM (STG * NSTAGE)   // 122880

template <int MODE>
__global__ void __launch_bounds__(256) gemm_mma(const float* __restrict__ bias) {
    extern __shared__ __align__(16) unsigned char smem[];
    const int tid  = threadIdx.x;
    const int lane = tid & 31;
    const int wid  = tid >> 5;
    const int wm   = wid & 3;
    const int wn   = wid >> 2;
    const int bm   = blockIdx.x * 128;
    const int bn   = blockIdx.y * 64;

    const __nv_bfloat16* __restrict__ Ah = (MODE == 0) ? g_H1h : g_D2h;
    const __nv_bfloat16* __restrict__ Al = (MODE == 0) ? g_H1l : g_D2l;
    const __nv_bfloat16* __restrict__ Bh = (MODE == 0) ? g_Bt0h : g_Bdvh;
    const __nv_bfloat16* __restrict__ Bl = (MODE == 0) ? g_Bt0l : g_Bdvl;

    const uint32_t sb = smem_u32(smem);

    const int crow = tid >> 2;                  // 0..63
    const int cg8  = (tid & 3) * 8;
    const size_t aoff1 = (size_t)(bm + crow) * H_SZ + cg8;
    const size_t aoff2 = (size_t)(bm + crow + 64) * H_SZ + cg8;
    const size_t boff  = (size_t)(bn + crow) * H_SZ + cg8;
    const uint32_t dR1 = crow * 80 + (tid & 3) * 16;
    const uint32_t dR2 = (crow + 64) * 80 + (tid & 3) * 16;

    float cacc[2][4][4] = {};

    const int lrow = (lane & 7) + ((lane >> 3) & 1) * 8;
    const int lcol = ((lane >> 4) & 1) * 16;

#define ISSUE(c) do {                                                           \
        const int _k0 = (c) * 32;                                               \
        const uint32_t _st = sb + ((c) & (NSTAGE - 1)) * STG;                   \
        cp16(_st + SA_H + dR1, Ah + aoff1 + _k0);                               \
        cp16(_st + SA_H + dR2, Ah + aoff2 + _k0);                               \
        cp16(_st + SA_L + dR1, Al + aoff1 + _k0);                               \
        cp16(_st + SA_L + dR2, Al + aoff2 + _k0);                               \
        cp16(_st + SB_H + dR1, Bh + boff + _k0);                                \
        cp16(_st + SB_L + dR1, Bl + boff + _k0);                                \
    } while (0)

    ISSUE(0); CP_COMMIT();
    ISSUE(1); CP_COMMIT();
    ISSUE(2); CP_COMMIT();

#pragma unroll 1
    for (int c = 0; c < 16; ++c) {
        CP_WAIT(2);
        __syncthreads();
        if (c + 3 < 16) ISSUE(c + 3);
        CP_COMMIT();

        const uint32_t st = sb + (c & (NSTAGE - 1)) * STG;
#pragma unroll
        for (int kk = 0; kk < 2; kk++) {
            uint32_t afh[2][4], afl[2][4], bfh[2][4], bfl[2][4];
#pragma unroll
            for (int m = 0; m < 2; m++) {
                uint32_t ad = st + SA_H +
                    (uint32_t)((wm * 32 + m * 16 + lrow) * 80 + lcol + kk * 32);
                LDSM4(afh[m], ad);
                LDSM4(afl[m], ad + (SA_L - SA_H));
            }
#pragma unroll
            for (int p = 0; p < 2; p++) {
                uint32_t bd = st + SB_H +
                    (uint32_t)((wn * 32 + p * 16 + lrow) * 80 + lcol + kk * 32);
                LDSM4(bfh[p], bd);
                LDSM4(bfl[p], bd + (SB_L - SB_H));
            }
#pragma unroll
            for (int m = 0; m < 2; m++)
#pragma unroll
                for (int n = 0; n < 4; n++) {
                    const int p = n >> 1, o = n & 1;
                    MMA_BF16(cacc[m][n], afh[m], bfh[p][o], bfh[p][o + 2]);
                }
#pragma unroll
            for (int m = 0; m < 2; m++)
#pragma unroll
                for (int n = 0; n < 4; n++) {
                    const int p = n >> 1, o = n & 1;
                    MMA_BF16(cacc[m][n], afh[m], bfl[p][o], bfl[p][o + 2]);
                }
#pragma unroll
            for (int m = 0; m < 2; m++)
#pragma unroll
                for (int n = 0; n < 4; n++) {
                    const int p = n >> 1, o = n & 1;
                    MMA_BF16(cacc[m][n], afl[m], bfh[p][o], bfh[p][o + 2]);
                }
        }
    }
#undef ISSUE

    __syncthreads();

    if (MODE == 0) {
#pragma unroll
        for (int m = 0; m < 2; m++)
#pragma unroll
            for (int h = 0; h < 2; h++) {
                const int row = bm + wm * 32 + m * 16 + (lane >> 2) + h * 8;
#pragma unroll
                for (int n = 0; n < 4; n++) {
                    const int col = bn + wn * 32 + n * 8 + ((lane & 3) << 1);
                    float v0 = tanhf(cacc[m][n][h * 2 + 0] + __ldg(&bias[col + 0]));
                    float v1 = tanhf(cacc[m][n][h * 2 + 1] + __ldg(&bias[col + 1]));
                    __nv_bfloat16 a0, a1, a2, a3;
                    bf16split(v0, a0, a1);
                    bf16split(v1, a2, a3);
                    *(__nv_bfloat162*)&g_H2h[(size_t)row * H_SZ + col] =
                        __nv_bfloat162(a0, a2);
                    *(__nv_bfloat162*)&g_H2l[(size_t)row * H_SZ + col] =
                        __nv_bfloat162(a1, a3);
                    float d0 = 1.f - v0 * v0, d1v = 1.f - v1 * v1;
                    __nv_bfloat16 h0, l0, h1b, l1;
                    bf16split(d0, h0, l0);
                    bf16split(d1v, h1b, l1);
                    *(__nv_bfloat162*)&g_D2h[(size_t)row * H_SZ + col] =
                        __nv_bfloat162(h0, h1b);
                    *(__nv_bfloat162*)&g_D2l[(size_t)row * H_SZ + col] =
                        __nv_bfloat162(l0, l1);
                }
            }
    } else {
        float sr[4] = {0.f, 0.f, 0.f, 0.f};
#pragma unroll
        for (int m = 0; m < 2; m++)
#pragma unroll
            for (int h = 0; h < 2; h++) {
                const int row = bm + wm * 32 + m * 16 + (lane >> 2) + h * 8;
#pragma unroll
                for (int n = 0; n < 4; n++) {
                    const int col = bn + wn * 32 + n * 8 + ((lane & 3) << 1);
                    float2 w = *(const float2*)&g_D1[(size_t)row * H_SZ + col];
                    sr[m * 2 + h] += w.x * cacc[m][n][h * 2 + 0]
                                   + w.y * cacc[m][n][h * 2 + 1];
                }
            }
#pragma unroll
        for (int i = 0; i < 4; i++) {
            sr[i] += __shfl_xor_sync(0xffffffffu, sr[i], 1);
            sr[i] += __shfl_xor_sync(0xffffffffu, sr[i], 2);
        }
        float* red = (float*)smem;
        if ((lane & 3) == 0) {
#pragma unroll
            for (int m = 0; m < 2; m++)
#pragma unroll
                for (int h = 0; h < 2; h++) {
                    const int rl = wm * 32 + m * 16 + (lane >> 2) + h * 8;
                    red[rl * 2 + wn] = sr[m * 2 + h];
                }
        }
        __syncthreads();
        if (tid < 128)
            g_divpart[blockIdx.y * B_SZ + bm + tid] = red[tid * 2] + red[tid * 2 + 1];
    }
}

// ---------------------------------------------------------------------------
// K4 (MMA, warp-independent K-split): dx = H2 @ W3 + b3.
// grid 128, 256 threads. CTA = 16 batch rows; warp w owns K slice
// [w*64, w*64+64) with a PRIVATE smem region (144B-pitch rows, conflict-free
// LDSM). Each warp: 24 cp.async -> wait own group -> 24 LDSM + 48 MMA.
// No CTA barrier until the final 8-warp reduction (+b3, +divergence).
// ---------------------------------------------------------------------------
#define K4_WSL  13824                // per-warp region
#define K4_AH   0                    // 16 rows * 144
#define K4_AL   2304
#define K4_BH   4608                 // 32 rows * 144
#define K4_BL   9216
#define K4_SMEM (K4_WSL * 8)         // 110592

__global__ void __launch_bounds__(256) k4_mma(const float* __restrict__ b3,
                                              float* __restrict__ out) {
    extern __shared__ __align__(16) unsigned char smem[];
    const int tid  = threadIdx.x;
    const int lane = tid & 31;
    const int wid  = tid >> 5;
    const int bm   = blockIdx.x * 16;
    const int ks   = wid * 64;           // this warp's K base (elements)

    const uint32_t wb = smem_u32(smem) + wid * K4_WSL;

    // ---- per-warp loads: A (H2 split, 16 rows x 64) = 8 cp16/lane
#pragma unroll
    for (int i = 0; i < 4; i++) {
        const int g = lane + 32 * i;         // 0..127
        const int row = g >> 3, q = g & 7;
        cp16(wb + K4_AH + row * 144 + q * 16,
             g_H2h + (size_t)(bm + row) * H_SZ + ks + q * 8);
        cp16(wb + K4_AL + row * 144 + q * 16,
             g_H2l + (size_t)(bm + row) * H_SZ + ks + q * 8);
    }
    // ---- B (W3t split, 32 rows x 64) = 16 cp16/lane
#pragma unroll
    for (int i = 0; i < 8; i++) {
        const int g = lane + 32 * i;         // 0..255
        const int row = g >> 3, q = g & 7;
        cp16(wb + K4_BH + row * 144 + q * 16, g_W3th + row * H_SZ + ks + q * 8);
        cp16(wb + K4_BL + row * 144 + q * 16, g_W3tl + row * H_SZ + ks + q * 8);
    }
    CP_COMMIT();
    CP_WAIT(0);
    __syncwarp();

    float cacc[4][4] = {};
    const int lr16  = lane & 15;
    const int lc16  = ((lane >> 4) & 1) * 16;

#pragma unroll
    for (int s = 0; s < 4; s++) {
        const uint32_t kb = (uint32_t)(s * 32);
        uint32_t afh[4], afl[4], bfh[2][4], bfl[2][4];
        {
            uint32_t ad = wb + K4_AH + (uint32_t)(lr16 * 144 + lc16) + kb;
            LDSM4(afh, ad);
            LDSM4(afl, ad + (K4_AL - K4_AH));
        }
#pragma unroll
        for (int p = 0; p < 2; p++) {
            uint32_t bd = wb + K4_BH +
                (uint32_t)((p * 16 + lr16) * 144 + lc16) + kb;
            LDSM4(bfh[p], bd);
            LDSM4(bfl[p], bd + (K4_BL - K4_BH));
        }
#pragma unroll
        for (int n = 0; n < 4; n++) {
            const int p = n >> 1, o = n & 1;
            MMA_BF16(cacc[n], afh, bfh[p][o], bfh[p][o + 2]);
        }
#pragma unroll
        for (int n = 0; n < 4; n++) {
            const int p = n >> 1, o = n & 1;
            MMA_BF16(cacc[n], afh, bfl[p][o], bfl[p][o + 2]);
        }
#pragma unroll
        for (int n = 0; n < 4; n++) {
            const int p = n >> 1, o = n & 1;
            MMA_BF16(cacc[n], afl, bfh[p][o], bfh[p][o + 2]);
        }
    }

    // ---- 8-warp reduction: red[w][16][32] floats (16KB, aliases warp regions)
    __syncthreads();
    float* red = (float*)smem;
    {
        const int r = lane >> 2;
        const int c0 = (lane & 3) << 1;
#pragma unroll
        for (int n = 0; n < 4; n++) {
            red[(wid * 16 + r) * 32 + n * 8 + c0]         = cacc[n][0];
            red[(wid * 16 + r) * 32 + n * 8 + c0 + 1]     = cacc[n][1];
            red[(wid * 16 + r + 8) * 32 + n * 8 + c0]     = cacc[n][2];
            red[(wid * 16 + r + 8) * 32 + n * 8 + c0 + 1] = cacc[n][3];
        }
    }
    __syncthreads();

#pragma unroll
    for (int i = 0; i < 2; i++) {
        const int idx = tid + 256 * i;       // 0..511
        const int row = idx >> 5, col = idx & 31;
        float s = 0.f;
#pragma unroll
        for (int w = 0; w < 8; w++) s += red[(w * 16 + row) * 32 + col];
        out[(bm + row) * 33 + col] = s + __ldg(&b3[col]);
    }
    if (tid < 16) {
        float s = 0.f;
#pragma unroll
        for (int p = 0; p < 8; p++) s += g_divpart[p * B_SZ + bm + tid];
        out[(bm + tid) * 33 + 32] = s;
    }
}

// ---------------------------------------------------------------------------
extern "C" void kernel_launch(void* const* d_in, const int* in_sizes, int n_in,
                              void* d_out, int out_size) {
    const float* t  = (const float*)d_in[0];
    const float* x  = (const float*)d_in[1];
    const float* W1 = (const float*)d_in[2];
    const float* b1 = (const float*)d_in[3];
    const float* W2 = (const float*)d_in[4];
    const float* b2 = (const float*)d_in[5];
    const float* W3 = (const float*)d_in[6];
    const float* b3 = (const float*)d_in[7];
    float* out = (float*)d_out;

    cudaFuncSetAttribute(gemm_mma<0>, cudaFuncAttributeMaxDynamicSharedMemorySize, GEMM_SMEM);
    cudaFuncSetAttribute(gemm_mma<1>, cudaFuncAttributeMaxDynamicSharedMemorySize, GEMM_SMEM);
    cudaFuncSetAttribute(k4_mma, cudaFuncAttributeMaxDynamicSharedMemorySize, K4_SMEM);

    k01_pre<<<384, 512>>>(t, x, W1, b1, W2, W3);
    dim3 g(16, 8);
    gemm_mma<0><<<g, 256, GEMM_SMEM>>>(b2);        // H2(split) = tanh(H1@W2+b2), D2 split
    gemm_mma<1><<<g, 256, GEMM_SMEM>>>(nullptr);   // divergence partials
    k4_mma<<<128, 256, K4_SMEM>>>(b3, out);        // dx + div finalize
}

// round 15
// speedup vs baseline: 1.0496x; 1.0496x over previous
#include <cuda_runtime.h>
#include <cuda_bf16.h>
#include <cstdint>

#define B_SZ 2048
#define H_SZ 512
#define D_SZ 32

// ---------------- scratch (device globals; no allocation allowed) ----------
__device__ __align__(16) __nv_bfloat16 g_H1h[B_SZ * H_SZ];
__device__ __align__(16) __nv_bfloat16 g_H1l[B_SZ * H_SZ];
__device__ __align__(16) float         g_D1 [B_SZ * H_SZ];   // 1 - h1^2
__device__ __align__(16) __nv_bfloat16 g_D2h[B_SZ * H_SZ];   // 1 - h2^2 split
__device__ __align__(16) __nv_bfloat16 g_D2l[B_SZ * H_SZ];
__device__ __align__(16) __nv_bfloat16 g_Bt0h[H_SZ * H_SZ];  // W2^T split
__device__ __align__(16) __nv_bfloat16 g_Bt0l[H_SZ * H_SZ];
__device__ __align__(16) __nv_bfloat16 g_Bdvh[H_SZ * H_SZ];  // E[n][k] split
__device__ __align__(16) __nv_bfloat16 g_Bdvl[H_SZ * H_SZ];
__device__ __align__(16) __nv_bfloat16 g_W3th[D_SZ * H_SZ];  // W3^T split [d][k]
__device__ __align__(16) __nv_bfloat16 g_W3tl[D_SZ * H_SZ];
__device__ __align__(16) float g_dxpart[16 * B_SZ * D_SZ];   // dx partials
__device__ float g_divpart[8 * B_SZ];

// ---------------- helpers ---------------------------------------------------
__device__ __forceinline__ void bf16split(float x, __nv_bfloat16& h, __nv_bfloat16& l) {
    h = __float2bfloat16_rn(x);
    l = __float2bfloat16_rn(x - __bfloat162float(h));
}
__device__ __forceinline__ uint32_t smem_u32(const void* p) {
    return (uint32_t)__cvta_generic_to_shared(p);
}
__device__ __forceinline__ void cp16(uint32_t dst, const void* src) {
    asm volatile("cp.async.cg.shared.global [%0], [%1], 16;" :: "r"(dst), "l"(src));
}
__device__ __forceinline__ uint32_t packbf(float a, float b) {
    __nv_bfloat162 v(__float2bfloat16_rn(a), __float2bfloat16_rn(b));
    return *(uint32_t*)&v;
}
#define CP_COMMIT() asm volatile("cp.async.commit_group;" ::: "memory")
#define CP_WAIT(n)  asm volatile("cp.async.wait_group %0;" :: "n"(n) : "memory")

#define LDSM4(d, addr)                                                          \
    asm volatile("ldmatrix.sync.aligned.m8n8.x4.shared.b16 {%0,%1,%2,%3}, [%4];"\
        : "=r"((d)[0]), "=r"((d)[1]), "=r"((d)[2]), "=r"((d)[3]) : "r"(addr))

#define MMA_BF16(c, a, b0v, b1v)                                                \
    asm volatile("mma.sync.aligned.m16n8k16.row.col.f32.bf16.bf16.f32 "         \
        "{%0,%1,%2,%3},{%4,%5,%6,%7},{%8,%9},{%0,%1,%2,%3};"                    \
        : "+f"((c)[0]), "+f"((c)[1]), "+f"((c)[2]), "+f"((c)[3])                 \
        : "r"((a)[0]), "r"((a)[1]), "r"((a)[2]), "r"((a)[3]), "r"(b0v), "r"(b1v))

// ---------------------------------------------------------------------------
// K01 (merged): blocks [0,128): H1/D1;  blocks [128,384): Bt0/Bdv (+W3t)
// ---------------------------------------------------------------------------
__global__ void __launch_bounds__(512) k01_pre(const float* __restrict__ t,
                                               const float* __restrict__ x,
                                               const float* __restrict__ W1,
                                               const float* __restrict__ b1,
                                               const float* __restrict__ W2,
                                               const float* __restrict__ W3) {
    __shared__ __align__(16) char sbuf[2 * 32 * 33 * 4];
    const int bx  = blockIdx.x;
    const int tid = threadIdx.x;

    if (bx < 128) {
        float (*sx)[33] = (float(*)[33])sbuf;
        const int b0 = bx * 16;
        const int m  = tid;
        for (int idx = m; idx < 16 * 33; idx += 512) {
            int r = idx / 33, j = idx % 33;
            sx[r][j] = (j == 32) ? t[0] : x[(b0 + r) * 33 + j];
        }
        float w[33];
#pragma unroll
        for (int j = 0; j < 33; j++) w[j] = W1[j * H_SZ + m];
        float bb = b1[m];
        __syncthreads();
#pragma unroll 4
        for (int r = 0; r < 16; r++) {
            float acc = bb;
#pragma unroll
            for (int j = 0; j < 33; j++) acc = fmaf(sx[r][j], w[j], acc);
            float h = tanhf(acc);
            const int o = (b0 + r) * H_SZ + m;
            bf16split(h, g_H1h[o], g_H1l[o]);
            g_D1[o] = 1.f - h * h;
        }
    } else {
        float (*tW2)[33] = (float(*)[33])sbuf;
        float (*sW3)[33] = (float(*)[33])(sbuf + 32 * 33 * 4);
        const int q  = bx - 128;
        const int kt = q & 15, nt = q >> 4;
        const int k0 = kt * 32, n0 = nt * 32;
        const int tx = tid & 31, tyh = tid >> 5;
#pragma unroll
        for (int yy = 0; yy < 2; yy++) {
            int ty = tyh + yy * 16;
            tW2[ty][tx] = W2[(k0 + ty) * H_SZ + n0 + tx];
            sW3[ty][tx] = W3[(k0 + ty) * D_SZ + tx];
        }
        __syncthreads();
#pragma unroll
        for (int yy = 0; yy < 2; yy++) {
            const int ty = tyh + yy * 16;
            const int n = n0 + ty;
            const int k = k0 + tx;
            bf16split(tW2[tx][ty], g_Bt0h[n * H_SZ + k], g_Bt0l[n * H_SZ + k]);
            float s = 0.f;
#pragma unroll
            for (int j = 0; j < D_SZ; j++)
                s = fmaf(W1[j * H_SZ + n], sW3[tx][j], s);
            bf16split(W2[n * H_SZ + k] * s, g_Bdvh[n * H_SZ + k], g_Bdvl[n * H_SZ + k]);
        }
        if (nt == 0) {
#pragma unroll
            for (int yy = 0; yy < 2; yy++) {
                const int d = tyh + yy * 16;
                bf16split(sW3[tx][d], g_W3th[d * H_SZ + k0 + tx],
                                      g_W3tl[d * H_SZ + k0 + tx]);
            }
        }
    }
}

// ---------------------------------------------------------------------------
// bf16-split mma.sync GEMM, cp.async 4-stage pipeline (r7 config, proven).
// CTA tile 128(M) x 64(N), K=512 in 16 chunks of 32. grid (16,8), 256 thr.
// 8 warps: 4m x 2n, warp tile 32x32.
// MODE 0: C = H1 @ W2 -> v = tanh(C+b2); D2 = 1-v^2 split stored;
//         dx partial = v @ W3t-slice fused via C->A fragment reuse.
// MODE 1: C = D2 @ E^T -> divpart[ny][row] = sum_col D1[row,col]*C[row,col]
// ---------------------------------------------------------------------------
#define SA_H 0
#define SA_L 10240
#define SB_H 20480
#define SB_L 25600
#define STG  30720
#define NSTAGE 4
#define W3_H (STG * NSTAGE)          // 122880, 32 rows x 144B
#define W3_L (W3_H + 4608)
#define GEMM_SMEM (W3_L + 4608)      // 132096

template <int MODE>
__global__ void __launch_bounds__(256) gemm_mma(const float* __restrict__ bias) {
    extern __shared__ __align__(16) unsigned char smem[];
    const int tid  = threadIdx.x;
    const int lane = tid & 31;
    const int wid  = tid >> 5;
    const int wm   = wid & 3;
    const int wn   = wid >> 2;
    const int bm   = blockIdx.x * 128;
    const int bn   = blockIdx.y * 64;

    const __nv_bfloat16* __restrict__ Ah = (MODE == 0) ? g_H1h : g_D2h;
    const __nv_bfloat16* __restrict__ Al = (MODE == 0) ? g_H1l : g_D2l;
    const __nv_bfloat16* __restrict__ Bh = (MODE == 0) ? g_Bt0h : g_Bdvh;
    const __nv_bfloat16* __restrict__ Bl = (MODE == 0) ? g_Bt0l : g_Bdvl;

    const uint32_t sb = smem_u32(smem);

    // MODE 0: preload W3t slice (32 d x 64 k at bn) in its own cp.async group
    if (MODE == 0) {
        const int d = tid >> 3, q = tid & 7;   // 256 thr = 32 rows x 8 granules
        cp16(sb + W3_H + d * 144 + q * 16, g_W3th + d * H_SZ + bn + q * 8);
        cp16(sb + W3_L + d * 144 + q * 16, g_W3tl + d * H_SZ + bn + q * 8);
        CP_COMMIT();
    }

    const int crow = tid >> 2;
    const int cg8  = (tid & 3) * 8;
    const size_t aoff1 = (size_t)(bm + crow) * H_SZ + cg8;
    const size_t aoff2 = (size_t)(bm + crow + 64) * H_SZ + cg8;
    const size_t boff  = (size_t)(bn + crow) * H_SZ + cg8;
    const uint32_t dR1 = crow * 80 + (tid & 3) * 16;
    const uint32_t dR2 = (crow + 64) * 80 + (tid & 3) * 16;

    float cacc[2][4][4] = {};

    const int lrow = (lane & 7) + ((lane >> 3) & 1) * 8;
    const int lcol = ((lane >> 4) & 1) * 16;

#define ISSUE(c) do {                                                           \
        const int _k0 = (c) * 32;                                               \
        const uint32_t _st = sb + ((c) & (NSTAGE - 1)) * STG;                   \
        cp16(_st + SA_H + dR1, Ah + aoff1 + _k0);                               \
        cp16(_st + SA_H + dR2, Ah + aoff2 + _k0);                               \
        cp16(_st + SA_L + dR1, Al + aoff1 + _k0);                               \
        cp16(_st + SA_L + dR2, Al + aoff2 + _k0);                               \
        cp16(_st + SB_H + dR1, Bh + boff + _k0);                                \
        cp16(_st + SB_L + dR1, Bl + boff + _k0);                                \
    } while (0)

    ISSUE(0); CP_COMMIT();
    ISSUE(1); CP_COMMIT();
    ISSUE(2); CP_COMMIT();

#pragma unroll 1
    for (int c = 0; c < 16; ++c) {
        CP_WAIT(2);
        __syncthreads();
        if (c + 3 < 16) ISSUE(c + 3);
        CP_COMMIT();

        const uint32_t st = sb + (c & (NSTAGE - 1)) * STG;
#pragma unroll
        for (int kk = 0; kk < 2; kk++) {
            uint32_t afh[2][4], afl[2][4], bfh[2][4], bfl[2][4];
#pragma unroll
            for (int m = 0; m < 2; m++) {
                uint32_t ad = st + SA_H +
                    (uint32_t)((wm * 32 + m * 16 + lrow) * 80 + lcol + kk * 32);
                LDSM4(afh[m], ad);
                LDSM4(afl[m], ad + (SA_L - SA_H));
            }
#pragma unroll
            for (int p = 0; p < 2; p++) {
                uint32_t bd = st + SB_H +
                    (uint32_t)((wn * 32 + p * 16 + lrow) * 80 + lcol + kk * 32);
                LDSM4(bfh[p], bd);
                LDSM4(bfl[p], bd + (SB_L - SB_H));
            }
#pragma unroll
            for (int m = 0; m < 2; m++)
#pragma unroll
                for (int n = 0; n < 4; n++) {
                    const int p = n >> 1, o = n & 1;
                    MMA_BF16(cacc[m][n], afh[m], bfh[p][o], bfh[p][o + 2]);
                }
#pragma unroll
            for (int m = 0; m < 2; m++)
#pragma unroll
                for (int n = 0; n < 4; n++) {
                    const int p = n >> 1, o = n & 1;
                    MMA_BF16(cacc[m][n], afh[m], bfl[p][o], bfl[p][o + 2]);
                }
#pragma unroll
            for (int m = 0; m < 2; m++)
#pragma unroll
                for (int n = 0; n < 4; n++) {
                    const int p = n >> 1, o = n & 1;
                    MMA_BF16(cacc[m][n], afl[m], bfh[p][o], bfh[p][o + 2]);
                }
        }
    }
#undef ISSUE

    __syncthreads();

    if (MODE == 0) {
        // v = tanh(C + b2); store D2 split; overwrite cacc with v.
#pragma unroll
        for (int m = 0; m < 2; m++)
#pragma unroll
            for (int h = 0; h < 2; h++) {
                const int row = bm + wm * 32 + m * 16 + (lane >> 2) + h * 8;
#pragma unroll
                for (int n = 0; n < 4; n++) {
                    const int col = bn + wn * 32 + n * 8 + ((lane & 3) << 1);
                    float v0 = tanhf(cacc[m][n][h * 2 + 0] + __ldg(&bias[col + 0]));
                    float v1 = tanhf(cacc[m][n][h * 2 + 1] + __ldg(&bias[col + 1]));
                    cacc[m][n][h * 2 + 0] = v0;
                    cacc[m][n][h * 2 + 1] = v1;
                    float d0 = 1.f - v0 * v0, d1v = 1.f - v1 * v1;
                    __nv_bfloat16 h0, l0, h1b, l1;
                    bf16split(d0, h0, l0);
                    bf16split(d1v, h1b, l1);
                    *(__nv_bfloat162*)&g_D2h[(size_t)row * H_SZ + col] =
                        __nv_bfloat162(h0, h1b);
                    *(__nv_bfloat162*)&g_D2l[(size_t)row * H_SZ + col] =
                        __nv_bfloat162(l0, l1);
                }
            }

        // --- fused dx partial: pack v as A fragments (hi/lo) ---
        uint32_t ah[2][2][4], al[2][2][4];
#pragma unroll
        for (int m = 0; m < 2; m++)
#pragma unroll
            for (int kk = 0; kk < 2; kk++) {
#pragma unroll
                for (int j = 0; j < 2; j++) {       // n8 block 2kk+j -> k8 half j
                    const int nb = 2 * kk + j;
#pragma unroll
                    for (int h = 0; h < 2; h++) {
                        float v0 = cacc[m][nb][h * 2 + 0];
                        float v1 = cacc[m][nb][h * 2 + 1];
                        float h0 = __bfloat162float(__float2bfloat16_rn(v0));
                        float h1 = __bfloat162float(__float2bfloat16_rn(v1));
                        ah[m][kk][j * 2 + h] = packbf(v0, v1);
                        al[m][kk][j * 2 + h] = packbf(v0 - h0, v1 - h1);
                    }
                }
            }

        CP_WAIT(0);          // W3 slice resident (done long ago)
        __syncwarp();

        float dacc[2][4][4] = {};
#pragma unroll
        for (int kk = 0; kk < 2; kk++) {
            uint32_t wfh[2][4], wfl[2][4];
#pragma unroll
            for (int p = 0; p < 2; p++) {
                uint32_t bd = sb + W3_H +
                    (uint32_t)((p * 16 + lrow) * 144 + wn * 64 + kk * 32 + lcol);
                LDSM4(wfh[p], bd);
                LDSM4(wfl[p], bd + (W3_L - W3_H));
            }
#pragma unroll
            for (int m = 0; m < 2; m++)
#pragma unroll
                for (int n = 0; n < 4; n++) {
                    const int p = n >> 1, o = n & 1;
                    MMA_BF16(dacc[m][n], ah[m][kk], wfh[p][o], wfh[p][o + 2]);
                }
#pragma unroll
            for (int m = 0; m < 2; m++)
#pragma unroll
                for (int n = 0; n < 4; n++) {
                    const int p = n >> 1, o = n & 1;
                    MMA_BF16(dacc[m][n], ah[m][kk], wfl[p][o], wfl[p][o + 2]);
                }
#pragma unroll
            for (int m = 0; m < 2; m++)
#pragma unroll
                for (int n = 0; n < 4; n++) {
                    const int p = n >> 1, o = n & 1;
                    MMA_BF16(dacc[m][n], al[m][kk], wfh[p][o], wfh[p][o + 2]);
                }
        }

        // write dx partials: slot = blockIdx.y*2 + wn
        float* dst = g_dxpart + (size_t)(blockIdx.y * 2 + wn) * B_SZ * D_SZ;
#pragma unroll
        for (int m = 0; m < 2; m++)
#pragma unroll
            for (int h = 0; h < 2; h++) {
                const int row = bm + wm * 32 + m * 16 + (lane >> 2) + h * 8;
#pragma unroll
                for (int n = 0; n < 4; n++) {
                    const int col = n * 8 + ((lane & 3) << 1);
                    *(float2*)&dst[row * D_SZ + col] =
                        make_float2(dacc[m][n][h * 2 + 0], dacc[m][n][h * 2 + 1]);
                }
            }
    } else {
        float sr[4] = {0.f, 0.f, 0.f, 0.f};
#pragma unroll
        for (int m = 0; m < 2; m++)
#pragma unroll
            for (int h = 0; h < 2; h++) {
                const int row = bm + wm * 32 + m * 16 + (lane >> 2) + h * 8;
#pragma unroll
                for (int n = 0; n < 4; n++) {
                    const int col = bn + wn * 32 + n * 8 + ((lane & 3) << 1);
                    float2 w = *(const float2*)&g_D1[(size_t)row * H_SZ + col];
                    sr[m * 2 + h] += w.x * cacc[m][n][h * 2 + 0]
                                   + w.y * cacc[m][n][h * 2 + 1];
                }
            }
#pragma unroll
        for (int i = 0; i < 4; i++) {
            sr[i] += __shfl_xor_sync(0xffffffffu, sr[i], 1);
            sr[i] += __shfl_xor_sync(0xffffffffu, sr[i], 2);
        }
        float* red = (float*)smem;
        if ((lane & 3) == 0) {
#pragma unroll
            for (int m = 0; m < 2; m++)
#pragma unroll
                for (int h = 0; h < 2; h++) {
                    const int rl = wm * 32 + m * 16 + (lane >> 2) + h * 8;
                    red[rl * 2 + wn] = sr[m * 2 + h];
                }
        }
        __syncthreads();
        if (tid < 128)
            g_divpart[blockIdx.y * B_SZ + bm + tid] = red[tid * 2] + red[tid * 2 + 1];
    }
}

// ---------------------------------------------------------------------------
// K4 (final gather): out[b][d] = b3[d] + sum_16 dxpart; out[b][32] = div sum.
// grid 256, 256 threads: CTA = 8 rows x 32 cols, pure coalesced reads.
// ---------------------------------------------------------------------------
__global__ void __launch_bounds__(256) k4_final(const float* __restrict__ b3,
                                                float* __restrict__ out) {
    const int tid = threadIdx.x;
    const int b0  = blockIdx.x * 8;
    const int row = b0 + (tid >> 5);
    const int col = tid & 31;
    float s0 = 0.f, s1 = 0.f;
#pragma unroll
    for (int p = 0; p < 16; p += 2) {
        s0 += g_dxpart[((size_t)p * B_SZ + row) * D_SZ + col];
        s1 += g_dxpart[((size_t)(p + 1) * B_SZ + row) * D_SZ + col];
    }
    out[row * 33 + col] = s0 + s1 + __ldg(&b3[col]);
    if (tid < 8) {
        const int b = b0 + tid;
        float s = 0.f;
#pragma unroll
        for (int p = 0; p < 8; p++) s += g_divpart[p * B_SZ + b];
        out[b * 33 + 32] = s;
    }
}

// ---------------------------------------------------------------------------
extern "C" void kernel_launch(void* const* d_in, const int* in_sizes, int n_in,
                              void* d_out, int out_size) {
    const float* t  = (const float*)d_in[0];
    const float* x  = (const float*)d_in[1];
    const float* W1 = (const float*)d_in[2];
    const float* b1 = (const float*)d_in[3];
    const float* W2 = (const float*)d_in[4];
    const float* b2 = (const float*)d_in[5];
    const float* W3 = (const float*)d_in[6];
    const float* b3 = (const float*)d_in[7];
    float* out = (float*)d_out;

    cudaFuncSetAttribute(gemm_mma<0>, cudaFuncAttributeMaxDynamicSharedMemorySize, GEMM_SMEM);
    cudaFuncSetAttribute(gemm_mma<1>, cudaFuncAttributeMaxDynamicSharedMemorySize, GEMM_SMEM);

    k01_pre<<<384, 512>>>(t, x, W1, b1, W2, W3);
    dim3 g(16, 8);
    gemm_mma<0><<<g, 256, GEMM_SMEM>>>(b2);        // v=tanh, D2 split, dx partials fused
    gemm_mma<1><<<g, 256, GEMM_SMEM>>>(nullptr);   // divergence partials
    k4_final<<<256, 256>>>(b3, out);               // gather + biases
}